// round 11
// baseline (speedup 1.0000x reference)
#include <cuda_runtime.h>
#include <stdint.h>

// Problem constants (fixed shapes per reference setup_inputs)
#define BT    512          // B*T rows of (N, C)
#define NTOK  197
#define CDIM  768
#define TFR   16
#define HALF  (CDIM / 2)
#define LN_EPS 1e-5f

#define ROW4      (NTOK * CDIM / 4)               // float4s per (b,t) slab = 37824
#define CLS4      (CDIM / 4)                      // 192 float4s per cls row
#define PATCH4    ((NTOK - 1) * CDIM / 4)         // 37632 patch float4s per slab
#define F4_PER_THREAD 3
#define F4_PER_BLOCK  (256 * F4_PER_THREAD)       // 768
#define BULK_PER_SLAB (PATCH4 / F4_PER_BLOCK)     // 49 (exact: 49*768 = 37632)

// ---------------------------------------------------------------------------
// Warp-collective: LayerNorm -> ReLU -> (C->2) linear -> tanh gates for the
// cls row of one (b,t). Every lane returns the final (g1, g2).
// ---------------------------------------------------------------------------
__device__ __forceinline__ void warp_gates(
    const float* __restrict__ x, int bt,
    const float* __restrict__ ln_gamma,
    const float* __restrict__ ln_beta,
    const float* __restrict__ fc_w,
    const float* __restrict__ fc_b,
    int lid, float& g1, float& g2)
{
    const float4* xr = (const float4*)(x + (size_t)bt * NTOK * CDIM);

    float4 v[6];
    float s = 0.f, s2 = 0.f;
#pragma unroll
    for (int k = 0; k < 6; k++) {
        v[k] = xr[lid + k * 32];
        s  += v[k].x + v[k].y + v[k].z + v[k].w;
        s2 += v[k].x * v[k].x + v[k].y * v[k].y
            + v[k].z * v[k].z + v[k].w * v[k].w;
    }
#pragma unroll
    for (int o = 16; o; o >>= 1) {
        s  += __shfl_xor_sync(0xffffffffu, s,  o);
        s2 += __shfl_xor_sync(0xffffffffu, s2, o);
    }
    const float mu   = s  * (1.f / CDIM);
    const float var  = s2 * (1.f / CDIM) - mu * mu;
    const float rstd = rsqrtf(var + LN_EPS);

    const float4* g4  = (const float4*)ln_gamma;
    const float4* b4  = (const float4*)ln_beta;
    const float4* w04 = (const float4*)fc_w;            // row 0
    const float4* w14 = (const float4*)(fc_w + CDIM);   // row 1

    float d0 = 0.f, d1 = 0.f;
#pragma unroll
    for (int k = 0; k < 6; k++) {
        const int f = lid + k * 32;
        const float4 g = g4[f], b = b4[f], w0 = w04[f], w1 = w14[f];
        float h;
        h = fmaxf((v[k].x - mu) * rstd * g.x + b.x, 0.f); d0 += h * w0.x; d1 += h * w1.x;
        h = fmaxf((v[k].y - mu) * rstd * g.y + b.y, 0.f); d0 += h * w0.y; d1 += h * w1.y;
        h = fmaxf((v[k].z - mu) * rstd * g.z + b.z, 0.f); d0 += h * w0.z; d1 += h * w1.z;
        h = fmaxf((v[k].w - mu) * rstd * g.w + b.w, 0.f); d0 += h * w0.w; d1 += h * w1.w;
    }
#pragma unroll
    for (int o = 16; o; o >>= 1) {
        d0 += __shfl_xor_sync(0xffffffffu, d0, o);
        d1 += __shfl_xor_sync(0xffffffffu, d1, o);
    }
    g1 = tanhf(d0 + fc_b[0]);
    g2 = tanhf(d1 + fc_b[1]);
}

// ---------------------------------------------------------------------------
// Fused kernel, 2D grid: gridDim.y = slab (b,t) in [0, BT),
//                        gridDim.x = BULK_PER_SLAB bulk blocks + 1 cls block.
//  Bulk blocks: EXACT decomposition — 768 consecutive patch float4s per
//               block (3 per thread), no predicates, no tail, shifts/adds
//               only.
//  Cls block (x == BULK_PER_SLAB): warps 0/1/2 compute gates for rows
//               bt / bt-1 / bt+1, then threads 0..191 write the mixed cls row.
// ---------------------------------------------------------------------------
__global__ __launch_bounds__(256) void fused_kernel(
    const float* __restrict__ xf,
    float* __restrict__ outf,
    const float* __restrict__ ln_gamma,
    const float* __restrict__ ln_beta,
    const float* __restrict__ fc_w,
    const float* __restrict__ fc_b)
{
    const float4* __restrict__ xin = (const float4*)xf;
    float4* __restrict__ out       = (float4*)outf;
    const int tid = threadIdx.x;
    const int bt  = blockIdx.y;                    // slab index 0..511

    if (blockIdx.x < BULK_PER_SLAB) {
        // ------------- bulk patch-copy path (exact, predicate-free) -------------
        const size_t base = (size_t)bt * ROW4 + CLS4
                          + blockIdx.x * F4_PER_BLOCK + tid;

        float4 v[F4_PER_THREAD];
#pragma unroll
        for (int k = 0; k < F4_PER_THREAD; k++)
            v[k] = __ldcs(xin + base + k * 256);
#pragma unroll
        for (int k = 0; k < F4_PER_THREAD; k++)
            __stcs(out + base + k * 256, v[k]);
        return;
    }

    // ---------------- cls row path ----------------
    const int t   = bt % TFR;
    const int wid = tid >> 5;
    const int lid = tid & 31;

    __shared__ float sg1_own, sg2_own, sg2_prev, sg1_next;

    if (wid == 0) {
        float g1, g2;
        warp_gates(xf, bt, ln_gamma, ln_beta, fc_w, fc_b, lid, g1, g2);
        if (lid == 0) { sg1_own = g1; sg2_own = g2; }
    } else if (wid == 1 && t > 0) {
        float g1, g2;
        warp_gates(xf, bt - 1, ln_gamma, ln_beta, fc_w, fc_b, lid, g1, g2);
        if (lid == 0) sg2_prev = g2;
    } else if (wid == 2 && t < TFR - 1) {
        float g1, g2;
        warp_gates(xf, bt + 1, ln_gamma, ln_beta, fc_w, fc_b, lid, g1, g2);
        if (lid == 0) sg1_next = g1;
    }
    __syncthreads();

    if (tid < CLS4) {
        const size_t i = (size_t)bt * ROW4 + tid;
        float4 val = xin[i];

        if (tid < HALF / 4) {
            // new_g2 = g2*(1 - gate2[bt]) + (t>0 ? gate2[bt-1]*g2[bt-1] : 0)
            const float r = 1.f - sg2_own;
            val.x *= r; val.y *= r; val.z *= r; val.w *= r;
            if (t > 0) {
                const float gp = sg2_prev;
                const float4 p = xin[i - (size_t)ROW4];
                val.x += gp * p.x; val.y += gp * p.y;
                val.z += gp * p.z; val.w += gp * p.w;
            }
        } else {
            // new_g1 = g1*(1 - gate1[bt]) + (t<T-1 ? gate1[bt+1]*g1[bt+1] : 0)
            const float r = 1.f - sg1_own;
            val.x *= r; val.y *= r; val.z *= r; val.w *= r;
            if (t < TFR - 1) {
                const float gn = sg1_next;
                const float4 q = xin[i + (size_t)ROW4];
                val.x += gn * q.x; val.y += gn * q.y;
                val.z += gn * q.z; val.w += gn * q.w;
            }
        }
        out[i] = val;
    }
}

// ---------------------------------------------------------------------------
extern "C" void kernel_launch(void* const* d_in, const int* in_sizes, int n_in,
                              void* d_out, int out_size)
{
    const float* x        = (const float*)d_in[0];
    const float* ln_gamma = (const float*)d_in[1];
    const float* ln_beta  = (const float*)d_in[2];
    const float* fc_w     = (const float*)d_in[3];
    const float* fc_b     = (const float*)d_in[4];
    // d_in[5] = num_frames (constant TFR=16 for this shape variant)

    dim3 grid(BULK_PER_SLAB + 1, BT, 1);
    fused_kernel<<<grid, 256>>>(x, (float*)d_out,
                                ln_gamma, ln_beta, fc_w, fc_b);
}